// round 14
// baseline (speedup 1.0000x reference)
#include <cuda_runtime.h>
#include <cuda_bf16.h>
#include <cstdint>

// SConv2dAvg as GEMM on HMMA (mma.sync bf16, 3-product double-bf16 split).
// D[o,n] = sum_k W[o,k] P[k,n];  n = b*16+px tile of 256; k' = (r*3+s)*64 + c.
// R5 engine, decoupled: B rows are warp-private (warp w gathers AND computes
// rows [32w,32w+32)), gather of chunk ch+1 interleaved into compute of ch,
// round g overwrites exactly the columns kq g just consumed -> single B buffer,
// no B barrier. Only A (shared 18KB slab) is double-buffered w/ 1 barrier/chunk.

#define Y_DIM   63
#define COUT    64
#define KTOT    576
#define THREADS 256

// smem: Bhi[256][144] @0, Blo[256][144] @36864, A bufs p=0,1 @73728+p*18432
//       (each A buf: hi 64x144 then lo 64x144)
#define BHI_OFF 0
#define BLO_OFF 36864
#define A_OFF   73728
#define A_BUF   18432
#define SMEM_TOTAL 110592

__device__ unsigned short g_Ahi[COUT * KTOT];
__device__ unsigned short g_Alo[COUT * KTOT];

__global__ void prep_A_kernel(const float* __restrict__ w) {
    int idx = blockIdx.x * 256 + threadIdx.x;
    if (idx >= COUT * KTOT) return;
    int o  = idx / KTOT;
    int kp = idx - o * KTOT;        // k' = rs*64 + c
    int rs = kp >> 6;
    int c  = kp & 63;
    float v = w[o * KTOT + c * 9 + rs];
    unsigned short hi;
    asm("cvt.rn.bf16.f32 %0, %1;" : "=h"(hi) : "f"(v));
    float rem = v - __uint_as_float(((unsigned)hi) << 16);
    unsigned short lo;
    asm("cvt.rn.bf16.f32 %0, %1;" : "=h"(lo) : "f"(rem));
    g_Ahi[idx] = hi;
    g_Alo[idx] = lo;
}

__device__ __forceinline__ uint32_t pack_bf16x2(float x, float y) {
    uint32_t r;
    asm("cvt.rn.satfinite.bf16x2.f32 %0, %2, %1;" : "=r"(r) : "f"(x), "f"(y));
    return r;
}

#define MMA(acc, a, b)                                                         \
    asm volatile("mma.sync.aligned.m16n8k16.row.col.f32.bf16.bf16.f32 "        \
        "{%0,%1,%2,%3}, {%4,%5,%6,%7}, {%8,%9}, {%0,%1,%2,%3};"                \
        : "+f"((acc)[0]), "+f"((acc)[1]), "+f"((acc)[2]), "+f"((acc)[3])       \
        : "r"((a)[0]), "r"((a)[1]), "r"((a)[2]), "r"((a)[3]),                  \
          "r"((b)[0]), "r"((b)[1]))

// load round g (16 c-values) of this thread's B row for plane base p
#define LDGV(v, g)                                                             \
    _Pragma("unroll") for (int j_ = 0; j_ < 16; j_++)                          \
        (v)[j_] = __ldg(p + ((((g) << 4) + j_) << 14));

// convert round g -> 32B hi + 32B lo into this thread's B row (cols of kq g)
#define CVTS(v, g) do {                                                        \
    uint32_t hp_[8], lp_[8];                                                   \
    _Pragma("unroll") for (int q_ = 0; q_ < 8; q_++) {                         \
        float a0_ = (v)[2 * q_], a1_ = (v)[2 * q_ + 1];                        \
        hp_[q_] = pack_bf16x2(a0_, a1_);                                       \
        float r0_ = a0_ - __uint_as_float(hp_[q_] << 16);                      \
        float r1_ = a1_ - __uint_as_float(hp_[q_] & 0xFFFF0000u);              \
        lp_[q_] = pack_bf16x2(r0_, r1_);                                       \
    }                                                                          \
    char* d_ = smem + BHI_OFF + tid * 144 + (g) * 32;                          \
    *(uint4*)d_        = make_uint4(hp_[0], hp_[1], hp_[2], hp_[3]);           \
    *(uint4*)(d_ + 16) = make_uint4(hp_[4], hp_[5], hp_[6], hp_[7]);           \
    char* e_ = d_ + (BLO_OFF - BHI_OFF);                                       \
    *(uint4*)e_        = make_uint4(lp_[0], lp_[1], lp_[2], lp_[3]);           \
    *(uint4*)(e_ + 16) = make_uint4(lp_[4], lp_[5], lp_[6], lp_[7]);           \
} while (0)

// load+store A slab for chunk i into buffer bu (1024 uint4 over 256 threads)
#define LDSTA(i, bu) do {                                                      \
    uint4 aa_[4];                                                              \
    _Pragma("unroll") for (int t_ = 0; t_ < 4; t_++) {                         \
        int e_ = tid + t_ * THREADS;                                           \
        int bsel_ = e_ >> 9;                                                   \
        int e2_ = e_ & 511;                                                    \
        int m_ = e2_ >> 3, q_ = e2_ & 7;                                       \
        aa_[t_] = *(const uint4*)((const char*)(bsel_ ? g_Alo : g_Ahi)         \
                                  + m_ * (KTOT * 2) + (i) * 128 + q_ * 16);    \
    }                                                                          \
    _Pragma("unroll") for (int t_ = 0; t_ < 4; t_++) {                         \
        int e_ = tid + t_ * THREADS;                                           \
        int bsel_ = e_ >> 9;                                                   \
        int e2_ = e_ & 511;                                                    \
        int m_ = e2_ >> 3, q_ = e2_ & 7;                                       \
        *(uint4*)(smem + A_OFF + (bu) * A_BUF + bsel_ * 9216                   \
                  + m_ * 144 + q_ * 16) = aa_[t_];                             \
    }                                                                          \
} while (0)

// one k16 step; A from buffer pointer Ab, B from the single warp-private buf
#define COMPUTE_KQ(kq) do {                                                    \
    uint32_t bh_[4][2], bl_[4][2];                                             \
    _Pragma("unroll") for (int nf = 0; nf < 4; nf++) {                         \
        const char* pb = smem + BHI_OFF                                        \
                       + (w * 32 + nf * 8 + fr) * 144 + (kq) * 32 + fq * 4;    \
        bh_[nf][0] = *(const uint32_t*)pb;                                     \
        bh_[nf][1] = *(const uint32_t*)(pb + 16);                              \
        bl_[nf][0] = *(const uint32_t*)(pb + (BLO_OFF - BHI_OFF));             \
        bl_[nf][1] = *(const uint32_t*)(pb + (BLO_OFF - BHI_OFF) + 16);        \
    }                                                                          \
    _Pragma("unroll") for (int mf = 0; mf < 4; mf++) {                         \
        const char* pa = Ab + (mf * 16 + fr) * 144 + (kq) * 32 + fq * 4;       \
        uint32_t ah_[4], al_[4];                                               \
        ah_[0] = *(const uint32_t*)pa;                                         \
        ah_[1] = *(const uint32_t*)(pa + 8 * 144);                             \
        ah_[2] = *(const uint32_t*)(pa + 16);                                  \
        ah_[3] = *(const uint32_t*)(pa + 8 * 144 + 16);                        \
        al_[0] = *(const uint32_t*)(pa + 9216);                                \
        al_[1] = *(const uint32_t*)(pa + 9216 + 8 * 144);                      \
        al_[2] = *(const uint32_t*)(pa + 9216 + 16);                           \
        al_[3] = *(const uint32_t*)(pa + 9216 + 8 * 144 + 16);                 \
        _Pragma("unroll") for (int nf = 0; nf < 4; nf++) {                     \
            MMA(acc[mf][nf], ah_, bh_[nf]);                                    \
            MMA(acc[mf][nf], ah_, bl_[nf]);                                    \
            MMA(acc[mf][nf], al_, bh_[nf]);                                    \
        }                                                                      \
    }                                                                          \
} while (0)

__global__ __launch_bounds__(THREADS, 2) void sconv_hmma_kernel(
    const float* __restrict__ input,
    const float* __restrict__ bias,
    const int*   __restrict__ selh,
    const int*   __restrict__ selw,
    float*       __restrict__ out)
{
    extern __shared__ char smem[];

    const int tid  = threadIdx.x;
    const int lane = tid & 31;
    const int w    = tid >> 5;
    const int fq   = lane & 3;
    const int fr   = lane >> 2;

    const int y   = blockIdx.x >> 2;
    const int px0 = (blockIdx.x & 3) * 16;

    // gather mapping: thread owns B row tid = b*16 + pxl (warp-private rows)
    const int b   = tid >> 4;
    const int pxl = tid & 15;
    const int pxc = min(px0 + pxl, Y_DIM - 1);
    const int sh  = selh[y * Y_DIM + pxc];
    const int sw  = selw[y * Y_DIM + pxc];
    const float* pbase = input + (b << 20) + (2 * y + sh) * 128 + 2 * pxc + sw;

    float acc[4][4][4];
#pragma unroll
    for (int i = 0; i < 4; i++)
#pragma unroll
        for (int j = 0; j < 4; j++)
#pragma unroll
            for (int q = 0; q < 4; q++) acc[i][j][q] = 0.f;

    // ---- prologue: chunk 0 -> A buf 0 + own B rows ----
    {
        LDSTA(0, 0);
        const float* p = pbase;     // plane (0,0)
        float v0[16], v1[16];
        LDGV(v0, 0);
        LDGV(v1, 1);
        CVTS(v0, 0);
        LDGV(v0, 2);
        CVTS(v1, 1);
        LDGV(v1, 3);
        CVTS(v0, 2);
        CVTS(v1, 3);
    }
    __syncthreads();

    // ---- main loop: compute ch; interleave gather of ch+1 into own B rows ----
    for (int ch = 0; ch < 9; ch++) {
        const char* Ab = smem + A_OFF + (ch & 1) * A_BUF;
        const bool more = (ch < 8);
        const int chn  = ch + 1;
        const float* p = pbase + (chn / 3) * 128 + (chn - (chn / 3) * 3);

        float v0[16], v1[16];
        if (more) LDGV(v0, 0);              // round 0 in flight under kq0
        COMPUTE_KQ(0);
        if (more) { CVTS(v0, 0); LDGV(v1, 1); }   // overwrite kq0 cols (consumed)
        COMPUTE_KQ(1);
        if (more) { CVTS(v1, 1); LDGV(v0, 2); }
        COMPUTE_KQ(2);
        if (more) { CVTS(v0, 2); LDGV(v1, 3); }
        COMPUTE_KQ(3);
        if (more) { CVTS(v1, 3); LDSTA(chn, chn & 1); }
        __syncthreads();                    // A buffer handoff only
    }

    // ---- epilogue: scalar stores (odd output strides) ----
    const int npx   = min(16, Y_DIM - px0);
    const int ybase = y * Y_DIM + px0;

#pragma unroll
    for (int mf = 0; mf < 4; mf++) {
        const int o = mf * 16 + fr;
        const float bo0 = __ldg(bias + o);
        const float bo8 = __ldg(bias + o + 8);
#pragma unroll
        for (int nf = 0; nf < 4; nf++) {
            int n    = w * 32 + nf * 8 + 2 * fq;
            int bcol = n >> 4;
            int pp   = n & 15;
            long base0 = ((long)(bcol * COUT + o)) * (Y_DIM * Y_DIM) + ybase + pp;
            long base8 = base0 + 8L * (Y_DIM * Y_DIM);
            if (pp < npx) {
                out[base0] = acc[mf][nf][0] + bo0;
                out[base8] = acc[mf][nf][2] + bo8;
            }
            if (pp + 1 < npx) {
                out[base0 + 1] = acc[mf][nf][1] + bo0;
                out[base8 + 1] = acc[mf][nf][3] + bo8;
            }
        }
    }
}

extern "C" void kernel_launch(void* const* d_in, const int* in_sizes, int n_in,
                              void* d_out, int out_size)
{
    const float* input  = (const float*)d_in[0];
    const float* weight = (const float*)d_in[1];
    const float* bias   = (const float*)d_in[2];
    const int*   selh   = (const int*)d_in[3];
    const int*   selw   = (const int*)d_in[4];
    float*       out    = (float*)d_out;

    cudaFuncSetAttribute(sconv_hmma_kernel,
                         cudaFuncAttributeMaxDynamicSharedMemorySize, SMEM_TOTAL);

    prep_A_kernel<<<(COUT * KTOT + 255) / 256, 256>>>(weight);
    sconv_hmma_kernel<<<Y_DIM * 4, THREADS, SMEM_TOTAL>>>(input, bias, selh, selw, out);
}

// round 15
// speedup vs baseline: 1.3609x; 1.3609x over previous
#include <cuda_runtime.h>
#include <cuda_fp16.h>
#include <cstdint>

// SConv2dAvg as GEMM on HMMA (mma.sync m16n8k16 fp16, 2-product split).
// D[o,n] = sum_k W[o,k] P[k,n];  n = b*16+px tile of 256; k' = (r*3+s)*64 + c.
// W single fp16; P split fp16 hi+lo:  out = Wf16*Phi + Wf16*Plo.
// Error ~ (W - Wf16)*P ~ 2^-11 rel (P-side split residual ~2^-22).
// Structure/layouts identical to the proven R5 kernel; 1/3 fewer MMAs.

#define Y_DIM   63
#define COUT    64
#define KTOT    576
#define THREADS 256

// smem bytes: Bhi[256][144] @0, Blo[256][144] @36864, A[64][144] @73728
#define BHI_OFF 0
#define BLO_OFF 36864
#define A_OFF   73728
#define SMEM_TOTAL 82944

// Weight fp16, k-major with k' reorder: [64][576]
__device__ unsigned short g_A[COUT * KTOT];

__global__ void prep_A_kernel(const float* __restrict__ w) {
    int idx = blockIdx.x * 256 + threadIdx.x;
    if (idx >= COUT * KTOT) return;
    int o  = idx / KTOT;
    int kp = idx - o * KTOT;        // k' = rs*64 + c
    int rs = kp >> 6;
    int c  = kp & 63;
    float v = w[o * KTOT + c * 9 + rs];
    g_A[idx] = __half_as_ushort(__float2half_rn(v));
}

__device__ __forceinline__ uint32_t pack_f16x2(__half lo, __half hi) {
    return (uint32_t)__half_as_ushort(lo) | ((uint32_t)__half_as_ushort(hi) << 16);
}

#define MMA(acc, a, b)                                                         \
    asm volatile("mma.sync.aligned.m16n8k16.row.col.f32.f16.f16.f32 "          \
        "{%0,%1,%2,%3}, {%4,%5,%6,%7}, {%8,%9}, {%0,%1,%2,%3};"                \
        : "+f"((acc)[0]), "+f"((acc)[1]), "+f"((acc)[2]), "+f"((acc)[3])       \
        : "r"((a)[0]), "r"((a)[1]), "r"((a)[2]), "r"((a)[3]),                  \
          "r"((b)[0]), "r"((b)[1]))

__global__ __launch_bounds__(THREADS, 2) void sconv_hmma_kernel(
    const float* __restrict__ input,
    const float* __restrict__ bias,
    const int*   __restrict__ selh,
    const int*   __restrict__ selw,
    float*       __restrict__ out)
{
    extern __shared__ char smem[];

    const int tid  = threadIdx.x;
    const int lane = tid & 31;
    const int w    = tid >> 5;
    const int fq   = lane & 3;
    const int fr   = lane >> 2;

    const int y   = blockIdx.x >> 2;
    const int px0 = (blockIdx.x & 3) * 16;

    // ---- gather mapping: thread owns B row tid = b*16 + pxl, 64 c per chunk ----
    const int b   = tid >> 4;
    const int pxl = tid & 15;
    const int pxc = min(px0 + pxl, Y_DIM - 1);
    const int sh  = selh[y * Y_DIM + pxc];
    const int sw  = selw[y * Y_DIM + pxc];
    const float* pbase = input + (b << 20) + (2 * y + sh) * 128 + 2 * pxc + sw;

    float acc[4][4][4];
#pragma unroll
    for (int i = 0; i < 4; i++)
#pragma unroll
        for (int j = 0; j < 4; j++)
#pragma unroll
            for (int q = 0; q < 4; q++) acc[i][j][q] = 0.f;

    for (int ch = 0; ch < 9; ch++) {
        __syncthreads();

        // ---- stage A chunk: 64 rows x 64 fp16 (128B) -> smem stride 144 ----
#pragma unroll
        for (int i = 0; i < 2; i++) {
            int e = tid + i * THREADS;          // 0..511
            int m = e >> 3;
            int q = e & 7;
            *(uint4*)(smem + A_OFF + m * 144 + q * 16) =
                *(const uint4*)((const char*)g_A + m * (KTOT * 2) + ch * 128 + q * 16);
        }

        // ---- gather this thread's 64 c-values, split fp16 hi/lo, store ----
        const float* p = pbase + (ch / 3) * 128 + (ch - (ch / 3) * 3);
#pragma unroll
        for (int cb = 0; cb < 8; cb++) {
            float v[8];
#pragma unroll
            for (int j = 0; j < 8; j++)
                v[j] = __ldg(p + ((cb * 8 + j) << 14));
            uint32_t hp[4], lp[4];
#pragma unroll
            for (int q = 0; q < 4; q++) {
                float a0 = v[2 * q], a1 = v[2 * q + 1];
                __half h0 = __float2half_rn(a0);
                __half h1 = __float2half_rn(a1);
                hp[q] = pack_f16x2(h0, h1);
                float r0 = a0 - __half2float(h0);
                float r1 = a1 - __half2float(h1);
                lp[q] = pack_f16x2(__float2half_rn(r0), __float2half_rn(r1));
            }
            *(uint4*)(smem + BHI_OFF + tid * 144 + cb * 16) = make_uint4(hp[0], hp[1], hp[2], hp[3]);
            *(uint4*)(smem + BLO_OFF + tid * 144 + cb * 16) = make_uint4(lp[0], lp[1], lp[2], lp[3]);
        }
        __syncthreads();

        // ---- compute: 4 k16 steps (R5 engine, 144B rows, conflict-free) ----
#pragma unroll
        for (int kq = 0; kq < 4; kq++) {
            uint32_t bh[4][2], bl[4][2];
#pragma unroll
            for (int nf = 0; nf < 4; nf++) {
                const char* pb = smem + BHI_OFF
                               + (w * 32 + nf * 8 + fr) * 144 + kq * 32 + fq * 4;
                bh[nf][0] = *(const uint32_t*)pb;
                bh[nf][1] = *(const uint32_t*)(pb + 16);
                bl[nf][0] = *(const uint32_t*)(pb + (BLO_OFF - BHI_OFF));
                bl[nf][1] = *(const uint32_t*)(pb + (BLO_OFF - BHI_OFF) + 16);
            }
#pragma unroll
            for (int mf = 0; mf < 4; mf++) {
                const char* pa = smem + A_OFF + (mf * 16 + fr) * 144 + kq * 32 + fq * 4;
                uint32_t ah[4];
                ah[0] = *(const uint32_t*)pa;
                ah[1] = *(const uint32_t*)(pa + 8 * 144);
                ah[2] = *(const uint32_t*)(pa + 16);
                ah[3] = *(const uint32_t*)(pa + 8 * 144 + 16);
#pragma unroll
                for (int nf = 0; nf < 4; nf++) {
                    MMA(acc[mf][nf], ah, bh[nf]);
                    MMA(acc[mf][nf], ah, bl[nf]);
                }
            }
        }
    }

    // ---- epilogue: scalar stores (odd output strides) ----
    const int npx   = min(16, Y_DIM - px0);
    const int ybase = y * Y_DIM + px0;

#pragma unroll
    for (int mf = 0; mf < 4; mf++) {
        const int o = mf * 16 + fr;
        const float bo0 = __ldg(bias + o);
        const float bo8 = __ldg(bias + o + 8);
#pragma unroll
        for (int nf = 0; nf < 4; nf++) {
            int n    = w * 32 + nf * 8 + 2 * fq;
            int bcol = n >> 4;
            int pp   = n & 15;
            long base0 = ((long)(bcol * COUT + o)) * (Y_DIM * Y_DIM) + ybase + pp;
            long base8 = base0 + 8L * (Y_DIM * Y_DIM);
            if (pp < npx) {
                out[base0] = acc[mf][nf][0] + bo0;
                out[base8] = acc[mf][nf][2] + bo8;
            }
            if (pp + 1 < npx) {
                out[base0 + 1] = acc[mf][nf][1] + bo0;
                out[base8 + 1] = acc[mf][nf][3] + bo8;
            }
        }
    }
}

extern "C" void kernel_launch(void* const* d_in, const int* in_sizes, int n_in,
                              void* d_out, int out_size)
{
    const float* input  = (const float*)d_in[0];
    const float* weight = (const float*)d_in[1];
    const float* bias   = (const float*)d_in[2];
    const int*   selh   = (const int*)d_in[3];
    const int*   selw   = (const int*)d_in[4];
    float*       out    = (float*)d_out;

    cudaFuncSetAttribute(sconv_hmma_kernel,
                         cudaFuncAttributeMaxDynamicSharedMemorySize, SMEM_TOTAL);

    prep_A_kernel<<<(COUT * KTOT + 255) / 256, 256>>>(weight);
    sconv_hmma_kernel<<<Y_DIM * 4, THREADS, SMEM_TOTAL>>>(input, bias, selh, selw, out);
}

// round 16
// speedup vs baseline: 1.6539x; 1.2153x over previous
#include <cuda_runtime.h>
#include <cuda_fp16.h>
#include <cstdint>

// SConv2dAvg as GEMM on HMMA (mma.sync m16n8k16 fp16, SINGLE product).
// D[o,n] = sum_k Wf16[o,k] Pf16[k,n];  n = b*16+px tile of 256; k' = (r*3+s)*64 + c.
// Error ~ 2^-11-scale from each operand quantization: measured W-only 2.1e-4,
// predicted total ~3e-4 << 1e-3 threshold.
// Structure/layouts identical to the proven R5/R15 kernel; half of R15's MMAs.

#define Y_DIM   63
#define COUT    64
#define KTOT    576
#define THREADS 256

// smem bytes: B[256][144] @0, A[64][144] @36864
#define B_OFF   0
#define A_OFF   36864
#define SMEM_TOTAL 46080

// Weight fp16, k-major with k' reorder: [64][576]
__device__ unsigned short g_A[COUT * KTOT];

__global__ void prep_A_kernel(const float* __restrict__ w) {
    int idx = blockIdx.x * 256 + threadIdx.x;
    if (idx >= COUT * KTOT) return;
    int o  = idx / KTOT;
    int kp = idx - o * KTOT;        // k' = rs*64 + c
    int rs = kp >> 6;
    int c  = kp & 63;
    float v = w[o * KTOT + c * 9 + rs];
    g_A[idx] = __half_as_ushort(__float2half_rn(v));
}

__device__ __forceinline__ uint32_t pack_f16x2(__half lo, __half hi) {
    return (uint32_t)__half_as_ushort(lo) | ((uint32_t)__half_as_ushort(hi) << 16);
}

#define MMA(acc, a, b)                                                         \
    asm volatile("mma.sync.aligned.m16n8k16.row.col.f32.f16.f16.f32 "          \
        "{%0,%1,%2,%3}, {%4,%5,%6,%7}, {%8,%9}, {%0,%1,%2,%3};"                \
        : "+f"((acc)[0]), "+f"((acc)[1]), "+f"((acc)[2]), "+f"((acc)[3])       \
        : "r"((a)[0]), "r"((a)[1]), "r"((a)[2]), "r"((a)[3]),                  \
          "r"((b)[0]), "r"((b)[1]))

__global__ __launch_bounds__(THREADS, 2) void sconv_hmma_kernel(
    const float* __restrict__ input,
    const float* __restrict__ bias,
    const int*   __restrict__ selh,
    const int*   __restrict__ selw,
    float*       __restrict__ out)
{
    extern __shared__ char smem[];

    const int tid  = threadIdx.x;
    const int lane = tid & 31;
    const int w    = tid >> 5;
    const int fq   = lane & 3;
    const int fr   = lane >> 2;

    const int y   = blockIdx.x >> 2;
    const int px0 = (blockIdx.x & 3) * 16;

    // ---- gather mapping: thread owns B row tid = b*16 + pxl, 64 c per chunk ----
    const int b   = tid >> 4;
    const int pxl = tid & 15;
    const int pxc = min(px0 + pxl, Y_DIM - 1);
    const int sh  = selh[y * Y_DIM + pxc];
    const int sw  = selw[y * Y_DIM + pxc];
    const float* pbase = input + (b << 20) + (2 * y + sh) * 128 + 2 * pxc + sw;

    float acc[4][4][4];
#pragma unroll
    for (int i = 0; i < 4; i++)
#pragma unroll
        for (int j = 0; j < 4; j++)
#pragma unroll
            for (int q = 0; q < 4; q++) acc[i][j][q] = 0.f;

    for (int ch = 0; ch < 9; ch++) {
        __syncthreads();

        // ---- stage A chunk: 64 rows x 64 fp16 (128B) -> smem stride 144 ----
#pragma unroll
        for (int i = 0; i < 2; i++) {
            int e = tid + i * THREADS;          // 0..511
            int m = e >> 3;
            int q = e & 7;
            *(uint4*)(smem + A_OFF + m * 144 + q * 16) =
                *(const uint4*)((const char*)g_A + m * (KTOT * 2) + ch * 128 + q * 16);
        }

        // ---- gather this thread's 64 c-values, convert fp16, store ----
        const float* p = pbase + (ch / 3) * 128 + (ch - (ch / 3) * 3);
#pragma unroll
        for (int cb = 0; cb < 8; cb++) {
            float v[8];
#pragma unroll
            for (int j = 0; j < 8; j++)
                v[j] = __ldg(p + ((cb * 8 + j) << 14));
            uint32_t hp[4];
#pragma unroll
            for (int q = 0; q < 4; q++)
                hp[q] = pack_f16x2(__float2half_rn(v[2 * q]),
                                   __float2half_rn(v[2 * q + 1]));
            *(uint4*)(smem + B_OFF + tid * 144 + cb * 16) =
                make_uint4(hp[0], hp[1], hp[2], hp[3]);
        }
        __syncthreads();

        // ---- compute: 4 k16 steps (R5 engine, 144B rows, conflict-free) ----
#pragma unroll
        for (int kq = 0; kq < 4; kq++) {
            uint32_t bh[4][2];
#pragma unroll
            for (int nf = 0; nf < 4; nf++) {
                const char* pb = smem + B_OFF
                               + (w * 32 + nf * 8 + fr) * 144 + kq * 32 + fq * 4;
                bh[nf][0] = *(const uint32_t*)pb;
                bh[nf][1] = *(const uint32_t*)(pb + 16);
            }
#pragma unroll
            for (int mf = 0; mf < 4; mf++) {
                const char* pa = smem + A_OFF + (mf * 16 + fr) * 144 + kq * 32 + fq * 4;
                uint32_t ah[4];
                ah[0] = *(const uint32_t*)pa;
                ah[1] = *(const uint32_t*)(pa + 8 * 144);
                ah[2] = *(const uint32_t*)(pa + 16);
                ah[3] = *(const uint32_t*)(pa + 8 * 144 + 16);
#pragma unroll
                for (int nf = 0; nf < 4; nf++)
                    MMA(acc[mf][nf], ah, bh[nf]);
            }
        }
    }

    // ---- epilogue: scalar stores (odd output strides) ----
    const int npx   = min(16, Y_DIM - px0);
    const int ybase = y * Y_DIM + px0;

#pragma unroll
    for (int mf = 0; mf < 4; mf++) {
        const int o = mf * 16 + fr;
        const float bo0 = __ldg(bias + o);
        const float bo8 = __ldg(bias + o + 8);
#pragma unroll
        for (int nf = 0; nf < 4; nf++) {
            int n    = w * 32 + nf * 8 + 2 * fq;
            int bcol = n >> 4;
            int pp   = n & 15;
            long base0 = ((long)(bcol * COUT + o)) * (Y_DIM * Y_DIM) + ybase + pp;
            long base8 = base0 + 8L * (Y_DIM * Y_DIM);
            if (pp < npx) {
                out[base0] = acc[mf][nf][0] + bo0;
                out[base8] = acc[mf][nf][2] + bo8;
            }
            if (pp + 1 < npx) {
                out[base0 + 1] = acc[mf][nf][1] + bo0;
                out[base8 + 1] = acc[mf][nf][3] + bo8;
            }
        }
    }
}

extern "C" void kernel_launch(void* const* d_in, const int* in_sizes, int n_in,
                              void* d_out, int out_size)
{
    const float* input  = (const float*)d_in[0];
    const float* weight = (const float*)d_in[1];
    const float* bias   = (const float*)d_in[2];
    const int*   selh   = (const int*)d_in[3];
    const int*   selw   = (const int*)d_in[4];
    float*       out    = (float*)d_out;

    cudaFuncSetAttribute(sconv_hmma_kernel,
                         cudaFuncAttributeMaxDynamicSharedMemorySize, SMEM_TOTAL);

    prep_A_kernel<<<(COUT * KTOT + 255) / 256, 256>>>(weight);
    sconv_hmma_kernel<<<Y_DIM * 4, THREADS, SMEM_TOTAL>>>(input, bias, selh, selw, out);
}

// round 17
// speedup vs baseline: 1.8576x; 1.1232x over previous
#include <cuda_runtime.h>
#include <cuda_fp16.h>
#include <cstdint>

// SConv2dAvg as GEMM on HMMA (mma.sync m16n8k16 fp16, single product).
// D[o,n] = sum_k Wf16[o,k] Pf16[k,n]; per CTA n = 8 batches x 16 px = 128 cols.
// K=576 as 3 r-supergroups of 192 (k' = r*192 + s*64 + c): one float2-pair
// load per (row,c) serves ALL THREE s-planes (columns 2px..2px+3), cutting
// gather L2 sector traffic ~3x vs per-(r,s)-chunk scattered 4B loads.

#define Y_DIM   63
#define COUT    64
#define KTOT    576
#define THREADS 256

// smem: B[128 rows][400B] @0 (384B data: s*128 + c*2), A[64][400B] @51200
#define B_OFF   0
#define A_OFF   51200
#define SMEM_TOTAL 76800

// Weight fp16, k' = r*192 + s*64 + c: [64][576]
__device__ unsigned short g_A[COUT * KTOT];

__global__ void prep_A_kernel(const float* __restrict__ w) {
    int idx = blockIdx.x * 256 + threadIdx.x;
    if (idx >= COUT * KTOT) return;
    int o   = idx / KTOT;
    int kp  = idx - o * KTOT;       // k' = r*192 + s*64 + c
    int r   = kp / 192;
    int rem = kp - r * 192;
    int s   = rem >> 6;
    int c   = rem & 63;
    float v = w[o * KTOT + c * 9 + r * 3 + s];
    g_A[idx] = __half_as_ushort(__float2half_rn(v));
}

__device__ __forceinline__ uint32_t pack_f16x2(float x, float y) {
    return (uint32_t)__half_as_ushort(__float2half_rn(x))
         | ((uint32_t)__half_as_ushort(__float2half_rn(y)) << 16);
}

#define MMA(acc, a, b)                                                         \
    asm volatile("mma.sync.aligned.m16n8k16.row.col.f32.f16.f16.f32 "          \
        "{%0,%1,%2,%3}, {%4,%5,%6,%7}, {%8,%9}, {%0,%1,%2,%3};"                \
        : "+f"((acc)[0]), "+f"((acc)[1]), "+f"((acc)[2]), "+f"((acc)[3])       \
        : "r"((a)[0]), "r"((a)[1]), "r"((a)[2]), "r"((a)[3]),                  \
          "r"((b)[0]), "r"((b)[1]))

__global__ __launch_bounds__(THREADS, 2) void sconv_hmma_kernel(
    const float* __restrict__ input,
    const float* __restrict__ bias,
    const int*   __restrict__ selh,
    const int*   __restrict__ selw,
    float*       __restrict__ out)
{
    extern __shared__ char smem[];

    const int tid  = threadIdx.x;
    const int lane = tid & 31;
    const int w    = tid >> 5;
    const int fq   = lane & 3;
    const int fr   = lane >> 2;

    // grid 504: y, x-tile, batch-half
    const int bid = blockIdx.x;
    const int y   = bid >> 3;
    const int xt  = (bid >> 1) & 3;
    const int bhh = bid & 1;
    const int px0 = xt * 16;

    // gather mapping: row = tid&127 (= b_local*16 + pxl), c-half h = tid>>7
    const int row = tid & 127;
    const int h   = tid >> 7;
    const int pxl = row & 15;
    const int pxc = min(px0 + pxl, Y_DIM - 1);
    const int sh  = selh[y * Y_DIM + pxc];
    const bool swb = (selw[y * Y_DIM + pxc] != 0);
    const int b   = (bhh << 3) + (row >> 4);
    // column base 2*pxc (even -> float2 aligned); sw handled by select
    const float* pb_row = input + (b << 20) + (2 * y + sh) * 128 + 2 * pxc;
    const int ch_base = h << 5;     // this thread's 32 c-values

    float acc[4][2][4];
#pragma unroll
    for (int i = 0; i < 4; i++)
#pragma unroll
        for (int j = 0; j < 2; j++)
#pragma unroll
            for (int q = 0; q < 4; q++) acc[i][j][q] = 0.f;

    for (int r = 0; r < 3; r++) {
        __syncthreads();    // prior supergroup fully consumed

        // ---- stage A: 64 rows x 384B (k=192 fp16), 1536 uint4 / 256 thr ----
#pragma unroll
        for (int i = 0; i < 6; i++) {
            int e = tid + i * THREADS;
            int m = e / 24, q = e - m * 24;
            *(uint4*)(smem + A_OFF + m * 400 + q * 16) =
                *(const uint4*)((const char*)g_A + m * (KTOT * 2) + r * 384 + q * 16);
        }

        // ---- gather: 32 c, one float2-pair per c serves s=0,1,2 ----
        const float* prow = pb_row + r * 128;
#pragma unroll
        for (int grp = 0; grp < 4; grp++) {
            float2 q0[8], q1[8];
#pragma unroll
            for (int j = 0; j < 8; j++) {
                long coff = (long)(ch_base + grp * 8 + j) << 14;
                q0[j] = __ldg((const float2*)(prow + coff));
                q1[j] = __ldg((const float2*)(prow + coff + 2));
            }
            uint32_t hs[3][4];
#pragma unroll
            for (int t = 0; t < 4; t++) {
                // c pair (2t, 2t+1): cols f0..f3 = 2px..2px+3; val_s = f[sw+s]
                float a0s0 = swb ? q0[2*t].y   : q0[2*t].x;
                float a0s1 = swb ? q1[2*t].x   : q0[2*t].y;
                float a0s2 = swb ? q1[2*t].y   : q1[2*t].x;
                float a1s0 = swb ? q0[2*t+1].y : q0[2*t+1].x;
                float a1s1 = swb ? q1[2*t+1].x : q0[2*t+1].y;
                float a1s2 = swb ? q1[2*t+1].y : q1[2*t+1].x;
                hs[0][t] = pack_f16x2(a0s0, a1s0);
                hs[1][t] = pack_f16x2(a0s1, a1s1);
                hs[2][t] = pack_f16x2(a0s2, a1s2);
            }
            char* dB = smem + B_OFF + row * 400 + (h << 6) + grp * 16;
#pragma unroll
            for (int s = 0; s < 3; s++)
                *(uint4*)(dB + s * 128) = make_uint4(hs[s][0], hs[s][1], hs[s][2], hs[s][3]);
        }
        __syncthreads();

        // ---- compute: 12 k16 steps over k=192 (400B rows, conflict-free) ----
#pragma unroll
        for (int kq = 0; kq < 12; kq++) {
            uint32_t bh[2][2];
#pragma unroll
            for (int nf = 0; nf < 2; nf++) {
                const char* pb = smem + B_OFF
                               + (w * 16 + nf * 8 + fr) * 400 + kq * 32 + fq * 4;
                bh[nf][0] = *(const uint32_t*)pb;
                bh[nf][1] = *(const uint32_t*)(pb + 16);
            }
#pragma unroll
            for (int mf = 0; mf < 4; mf++) {
                const char* pa = smem + A_OFF + (mf * 16 + fr) * 400 + kq * 32 + fq * 4;
                uint32_t ah[4];
                ah[0] = *(const uint32_t*)pa;
                ah[1] = *(const uint32_t*)(pa + 8 * 400);
                ah[2] = *(const uint32_t*)(pa + 16);
                ah[3] = *(const uint32_t*)(pa + 8 * 400 + 16);
#pragma unroll
                for (int nf = 0; nf < 2; nf++)
                    MMA(acc[mf][nf], ah, bh[nf]);
            }
        }
    }

    // ---- epilogue: scalar stores (odd output strides) ----
    const int npx   = min(16, Y_DIM - px0);
    const int ybase = y * Y_DIM + px0;
    const int bb    = (bhh << 3) + w;       // warp owns one batch

#pragma unroll
    for (int mf = 0; mf < 4; mf++) {
        const int o = mf * 16 + fr;
        const float bo0 = __ldg(bias + o);
        const float bo8 = __ldg(bias + o + 8);
#pragma unroll
        for (int nf = 0; nf < 2; nf++) {
            int pp = nf * 8 + 2 * fq;
            long base0 = ((long)(bb * COUT + o)) * (Y_DIM * Y_DIM) + ybase + pp;
            long base8 = base0 + 8L * (Y_DIM * Y_DIM);
            if (pp < npx) {
                out[base0] = acc[mf][nf][0] + bo0;
                out[base8] = acc[mf][nf][2] + bo8;
            }
            if (pp + 1 < npx) {
                out[base0 + 1] = acc[mf][nf][1] + bo0;
                out[base8 + 1] = acc[mf][nf][3] + bo8;
            }
        }
    }
}

extern "C" void kernel_launch(void* const* d_in, const int* in_sizes, int n_in,
                              void* d_out, int out_size)
{
    const float* input  = (const float*)d_in[0];
    const float* weight = (const float*)d_in[1];
    const float* bias   = (const float*)d_in[2];
    const int*   selh   = (const int*)d_in[3];
    const int*   selw   = (const int*)d_in[4];
    float*       out    = (float*)d_out;

    cudaFuncSetAttribute(sconv_hmma_kernel,
                         cudaFuncAttributeMaxDynamicSharedMemorySize, SMEM_TOTAL);

    prep_A_kernel<<<(COUT * KTOT + 255) / 256, 256>>>(weight);
    sconv_hmma_kernel<<<Y_DIM * 8, THREADS, SMEM_TOTAL>>>(input, bias, selh, selw, out);
}